// round 6
// baseline (speedup 1.0000x reference)
#include <cuda_runtime.h>
#include <cstdint>

#define NEURONS  4096
#define KSEL     512
#define NTHREADS 256
#define VPT      4                 // float4 loads per thread (16 elems/thread)
#define NWARPS   (NTHREADS / 32)
#define FC_CAP   256
#define SENT     0xFFFFFFFFu

// histogram window: threshold for K/N=0.125 on N(0,1) is ~1.150 +- 0.025 (row std);
// [1.0, 1.3) is a ~6-sigma window. Anything else exercises the exact fallback.
#define H_LO     1.0f
#define H_SCALE  (256.0f / 0.3f)

// ---- monotone float<->key transform (fallback path only) ----
static __device__ __forceinline__ uint32_t f2key(uint32_t u) {
    return u ^ (uint32_t)(((int32_t)u >> 31) | 0x80000000u);
}
static __device__ __forceinline__ float key2f(uint32_t k) {
    uint32_t m = (uint32_t)((int32_t)k >> 31);
    return __uint_as_float(k ^ (0x80000000u | ~m));
}

// Block suffix-scan (descending bins) over a single 256-bin histogram; the thread
// whose bin the cumulative count crosses kk writes {bin, residual-k, bin-count}.
// Caller: hist fully written + sh_bin preset to SENT + __syncthreads() done.
static __device__ __forceinline__ void scan256(
    const uint32_t* hist, uint32_t* warp_pref,
    uint32_t base, uint32_t kk,
    uint32_t* sh_bin, uint32_t* sh_krem, uint32_t* sh_cnt,
    int tid, int lane, int wid)
{
    const int bin = 255 - tid;             // tid order == descending bins
    uint32_t h = hist[bin];
    uint32_t x = h;
    #pragma unroll
    for (int off = 1; off < 32; off <<= 1) {
        uint32_t y = __shfl_up_sync(0xFFFFFFFFu, x, off);
        if (lane >= off) x += y;
    }
    if (lane == 31) warp_pref[wid] = x;
    __syncthreads();
    if (wid == 0) {
        uint32_t t = (lane < NWARPS) ? warp_pref[lane] : 0u;
        #pragma unroll
        for (int off = 1; off < NWARPS; off <<= 1) {
            uint32_t y = __shfl_up_sync(0xFFFFFFFFu, t, off);
            if (lane >= off) t += y;
        }
        if (lane < NWARPS) warp_pref[lane] = t;
    }
    __syncthreads();
    uint32_t incl = base + x + (wid ? warp_pref[wid - 1] : 0u);
    uint32_t excl = incl - h;
    if (kk > excl && kk <= incl) {
        *sh_bin = (uint32_t)bin; *sh_krem = kk - excl; *sh_cnt = h;
    }
    __syncthreads();
}

__global__ void __launch_bounds__(NTHREADS, 6)
kwinners_kernel(const float* __restrict__ s, float* __restrict__ out)
{
    __shared__ uint32_t hist[256];
    __shared__ float    hval[256];          // one representative value per bin
    __shared__ uint32_t warp_pref[NWARPS];
    __shared__ uint32_t wabove[NWARPS];
    __shared__ float    fcand[FC_CAP];
    __shared__ uint32_t sh_bin, sh_krem, sh_cnt, sh_fcnt;
    __shared__ float    sh_T;

    const int tid  = threadIdx.x;
    const int lane = tid & 31;
    const int wid  = tid >> 5;
    const unsigned FULL = 0xFFFFFFFFu;

    const size_t row = blockIdx.x;
    const float4* __restrict__ src = reinterpret_cast<const float4*>(s)  + row * (NEURONS / 4);
    float4* __restrict__       dst = reinterpret_cast<float4*>(out)      + row * (NEURONS / 4);

    hist[tid] = 0u;
    if (tid == 0) { sh_bin = SENT; sh_fcnt = 0u; }
    __syncthreads();

    // ---- pass 1: sparse histogram in window, register count above window ----
    // Single monotone classifier: b = floor((x - H_LO) * H_SCALE).
    //   b >= 256 -> above window; 0 <= b < 256 -> histogram; b < 0 -> below (ignored)
    unsigned above = 0;
    #pragma unroll
    for (int i = 0; i < VPT; i++) {
        float4 v = src[tid + i * NTHREADS];
        float xs[4] = {v.x, v.y, v.z, v.w};
        #pragma unroll
        for (int j = 0; j < 4; j++) {
            float x = xs[j];
            int b = __float2int_rd((x - H_LO) * H_SCALE);
            above += (b >= 256);
            if ((unsigned)b < 256u) { atomicAdd(&hist[b], 1u); hval[b] = x; }
        }
    }
    above = __reduce_add_sync(FULL, above);
    if (lane == 0) wabove[wid] = above;
    __syncthreads();

    uint32_t base = 0;
    #pragma unroll
    for (int w = 0; w < NWARPS; w++) base += wabove[w];

    scan256(hist, warp_pref, base, KSEL, &sh_bin, &sh_krem, &sh_cnt, tid, lane, wid);

    float T;
    const uint32_t B = sh_bin;
    if (B != SENT && sh_cnt <= FC_CAP) {
        const uint32_t krem = sh_krem;
        const uint32_t cnt  = sh_cnt;
        if (cnt == 1u) {
            T = hval[B];                     // sole element of crossing bin
        } else {
            // collect the few bin-B elements, exact rank-select among them
            #pragma unroll
            for (int i = 0; i < VPT; i++) {
                float4 v = src[tid + i * NTHREADS];
                float xs[4] = {v.x, v.y, v.z, v.w};
                #pragma unroll
                for (int j = 0; j < 4; j++) {
                    float x = xs[j];
                    int b = __float2int_rd((x - H_LO) * H_SCALE);
                    if (b == (int)B) { uint32_t p = atomicAdd(&sh_fcnt, 1u); fcand[p] = x; }
                }
            }
            __syncthreads();
            const int n = (int)sh_fcnt;      // == cnt <= FC_CAP
            if (tid < n) {
                float mine = fcand[tid];
                int g = 0, eq = 0;
                for (int j = 0; j < n; j++) {
                    float o = fcand[j];
                    g  += (o > mine);
                    eq += (o == mine);
                }
                if ((uint32_t)g < krem && (uint32_t)(g + eq) >= krem) sh_T = mine;
            }
            __syncthreads();
            T = sh_T;
        }
    } else {
        // ---- exact 4-pass radix-select fallback (window miss / huge tie mass) ----
        uint32_t prefix = 0, kk = KSEL;
        for (int shift = 24; shift >= 0; shift -= 8) {
            hist[tid] = 0u;
            if (tid == 0) sh_bin = SENT;
            __syncthreads();
            #pragma unroll
            for (int i = 0; i < VPT; i++) {
                float4 v = src[tid + i * NTHREADS];
                float xs[4] = {v.x, v.y, v.z, v.w};
                #pragma unroll
                for (int j = 0; j < 4; j++) {
                    uint32_t key = f2key(__float_as_uint(xs[j]));
                    bool valid = (shift == 24) || ((key >> (shift + 8)) == prefix);
                    if (valid) atomicAdd(&hist[(key >> shift) & 0xFFu], 1u);
                }
            }
            __syncthreads();
            scan256(hist, warp_pref, 0u, kk, &sh_bin, &sh_krem, &sh_cnt, tid, lane, wid);
            prefix = (prefix << 8) | sh_bin;
            kk = sh_krem;
        }
        T = key2f(prefix);
    }

    // ---- apply threshold (float `>=` matches reference exactly) ----
    #pragma unroll
    for (int i = 0; i < VPT; i++) {
        float4 v = src[tid + i * NTHREADS];
        float4 o;
        o.x = (v.x >= T) ? v.x : 0.0f;
        o.y = (v.y >= T) ? v.y : 0.0f;
        o.z = (v.z >= T) ? v.z : 0.0f;
        o.w = (v.w >= T) ? v.w : 0.0f;
        dst[tid + i * NTHREADS] = o;
    }
}

extern "C" void kernel_launch(void* const* d_in, const int* in_sizes, int n_in,
                              void* d_out, int out_size)
{
    const float* s = (const float*)d_in[0];
    float* out = (float*)d_out;
    const int rows = out_size / NEURONS;   // 16384
    kwinners_kernel<<<rows, NTHREADS>>>(s, out);
}

// round 7
// speedup vs baseline: 1.0191x; 1.0191x over previous
#include <cuda_runtime.h>
#include <cstdint>

#define NEURONS  4096
#define KSEL     512
#define NTHREADS 256
#define VPT      4                 // float4 loads per thread (16 elems/thread)
#define NWARPS   (NTHREADS / 32)
#define FC_CAP   256
#define SENT     0xFFFFFFFFu

// histogram window: threshold for K/N=0.125 on N(0,1) is ~1.150 +- 0.025 (row std);
// [1.0, 1.3) is a ~6-sigma window. Anything else exercises the exact fallback.
#define H_LO     1.0f
#define H_SCALE  (256.0f / 0.3f)

// ---- monotone float<->key transform (fallback path only) ----
static __device__ __forceinline__ uint32_t f2key(uint32_t u) {
    return u ^ (uint32_t)(((int32_t)u >> 31) | 0x80000000u);
}
static __device__ __forceinline__ float key2f(uint32_t k) {
    uint32_t m = (uint32_t)((int32_t)k >> 31);
    return __uint_as_float(k ^ (0x80000000u | ~m));
}

// Block suffix-scan (descending bins) over a single 256-bin histogram; the thread
// whose bin the cumulative count crosses kk writes {bin, residual-k, bin-count}.
// Caller: hist fully written + sh_bin preset to SENT + __syncthreads() done.
static __device__ __forceinline__ void scan256(
    const uint32_t* hist, uint32_t* warp_pref,
    uint32_t base, uint32_t kk,
    uint32_t* sh_bin, uint32_t* sh_krem, uint32_t* sh_cnt,
    int tid, int lane, int wid)
{
    const int bin = 255 - tid;             // tid order == descending bins
    uint32_t h = hist[bin];
    uint32_t x = h;
    #pragma unroll
    for (int off = 1; off < 32; off <<= 1) {
        uint32_t y = __shfl_up_sync(0xFFFFFFFFu, x, off);
        if (lane >= off) x += y;
    }
    if (lane == 31) warp_pref[wid] = x;
    __syncthreads();
    if (wid == 0) {
        uint32_t t = (lane < NWARPS) ? warp_pref[lane] : 0u;
        #pragma unroll
        for (int off = 1; off < NWARPS; off <<= 1) {
            uint32_t y = __shfl_up_sync(0xFFFFFFFFu, t, off);
            if (lane >= off) t += y;
        }
        if (lane < NWARPS) warp_pref[lane] = t;
    }
    __syncthreads();
    uint32_t incl = base + x + (wid ? warp_pref[wid - 1] : 0u);
    uint32_t excl = incl - h;
    if (kk > excl && kk <= incl) {
        *sh_bin = (uint32_t)bin; *sh_krem = kk - excl; *sh_cnt = h;
    }
    __syncthreads();
}

__global__ void __launch_bounds__(NTHREADS, 6)
kwinners_kernel(const float* __restrict__ s, float* __restrict__ out)
{
    __shared__ uint32_t hist[256];
    __shared__ float    hval[256];          // one representative value per bin
    __shared__ uint32_t warp_pref[NWARPS];
    __shared__ uint32_t wabove[NWARPS];
    __shared__ float    fcand[FC_CAP];
    __shared__ uint32_t sh_bin, sh_krem, sh_cnt, sh_fcnt;
    __shared__ float    sh_T;

    const int tid  = threadIdx.x;
    const int lane = tid & 31;
    const int wid  = tid >> 5;
    const unsigned FULL = 0xFFFFFFFFu;

    const size_t row = blockIdx.x;
    const float4* __restrict__ src = reinterpret_cast<const float4*>(s)  + row * (NEURONS / 4);
    float4* __restrict__       dst = reinterpret_cast<float4*>(out)      + row * (NEURONS / 4);

    hist[tid] = 0u;
    if (tid == 0) { sh_bin = SENT; sh_fcnt = 0u; }
    __syncthreads();

    // ---- pass 1: sparse histogram in window, register count above window ----
    // Single monotone classifier: b = floor((x - H_LO) * H_SCALE).
    //   b >= 256 -> above window; 0 <= b < 256 -> histogram; b < 0 -> below (ignored)
    unsigned above = 0;
    #pragma unroll
    for (int i = 0; i < VPT; i++) {
        float4 v = src[tid + i * NTHREADS];
        float xs[4] = {v.x, v.y, v.z, v.w};
        #pragma unroll
        for (int j = 0; j < 4; j++) {
            float x = xs[j];
            int b = __float2int_rd((x - H_LO) * H_SCALE);
            above += (b >= 256);
            if ((unsigned)b < 256u) { atomicAdd(&hist[b], 1u); hval[b] = x; }
        }
    }
    above = __reduce_add_sync(FULL, above);
    if (lane == 0) wabove[wid] = above;
    __syncthreads();

    uint32_t base = 0;
    #pragma unroll
    for (int w = 0; w < NWARPS; w++) base += wabove[w];

    scan256(hist, warp_pref, base, KSEL, &sh_bin, &sh_krem, &sh_cnt, tid, lane, wid);

    float T;
    const uint32_t B = sh_bin;
    if (B != SENT && sh_cnt <= FC_CAP) {
        const uint32_t krem = sh_krem;
        const uint32_t cnt  = sh_cnt;
        if (cnt == 1u) {
            T = hval[B];                     // sole element of crossing bin
        } else {
            // collect the few bin-B elements, exact rank-select among them
            #pragma unroll
            for (int i = 0; i < VPT; i++) {
                float4 v = src[tid + i * NTHREADS];
                float xs[4] = {v.x, v.y, v.z, v.w};
                #pragma unroll
                for (int j = 0; j < 4; j++) {
                    float x = xs[j];
                    int b = __float2int_rd((x - H_LO) * H_SCALE);
                    if (b == (int)B) { uint32_t p = atomicAdd(&sh_fcnt, 1u); fcand[p] = x; }
                }
            }
            __syncthreads();
            const int n = (int)sh_fcnt;      // == cnt <= FC_CAP
            if (tid < n) {
                float mine = fcand[tid];
                int g = 0, eq = 0;
                for (int j = 0; j < n; j++) {
                    float o = fcand[j];
                    g  += (o > mine);
                    eq += (o == mine);
                }
                if ((uint32_t)g < krem && (uint32_t)(g + eq) >= krem) sh_T = mine;
            }
            __syncthreads();
            T = sh_T;
        }
    } else {
        // ---- exact 4-pass radix-select fallback (window miss / huge tie mass) ----
        uint32_t prefix = 0, kk = KSEL;
        for (int shift = 24; shift >= 0; shift -= 8) {
            hist[tid] = 0u;
            if (tid == 0) sh_bin = SENT;
            __syncthreads();
            #pragma unroll
            for (int i = 0; i < VPT; i++) {
                float4 v = src[tid + i * NTHREADS];
                float xs[4] = {v.x, v.y, v.z, v.w};
                #pragma unroll
                for (int j = 0; j < 4; j++) {
                    uint32_t key = f2key(__float_as_uint(xs[j]));
                    bool valid = (shift == 24) || ((key >> (shift + 8)) == prefix);
                    if (valid) atomicAdd(&hist[(key >> shift) & 0xFFu], 1u);
                }
            }
            __syncthreads();
            scan256(hist, warp_pref, 0u, kk, &sh_bin, &sh_krem, &sh_cnt, tid, lane, wid);
            prefix = (prefix << 8) | sh_bin;
            kk = sh_krem;
        }
        T = key2f(prefix);
    }

    // ---- apply threshold (float `>=` matches reference exactly) ----
    #pragma unroll
    for (int i = 0; i < VPT; i++) {
        float4 v = src[tid + i * NTHREADS];
        float4 o;
        o.x = (v.x >= T) ? v.x : 0.0f;
        o.y = (v.y >= T) ? v.y : 0.0f;
        o.z = (v.z >= T) ? v.z : 0.0f;
        o.w = (v.w >= T) ? v.w : 0.0f;
        dst[tid + i * NTHREADS] = o;
    }
}

extern "C" void kernel_launch(void* const* d_in, const int* in_sizes, int n_in,
                              void* d_out, int out_size)
{
    const float* s = (const float*)d_in[0];
    float* out = (float*)d_out;
    const int rows = out_size / NEURONS;   // 16384
    kwinners_kernel<<<rows, NTHREADS>>>(s, out);
}

// round 8
// speedup vs baseline: 1.0910x; 1.0705x over previous
#include <cuda_runtime.h>
#include <cstdint>

#define NEURONS  4096
#define KSEL     512
#define NTHREADS 256
#define VPT      4                 // float4 loads per thread (16 elems/thread)
#define NWARPS   (NTHREADS / 32)
#define FC_CAP   256
#define SENT     0xFFFFFFFFu

// Integer-domain histogram window (bit-monotone for positive floats):
// bins of width 2^13 ulps starting at 0x3F866000 (~1.0498), 256 bins -> hi ~1.2998.
// Threshold for K/N=0.125 on N(0,1) rows is 1.150 +- 0.025 => +-5 sigma window.
#define WIN_SHIFT 13
#define WIN_BASE  (0x3F866000 >> WIN_SHIFT)

// ---- monotone float<->key transform (fallback path only) ----
static __device__ __forceinline__ uint32_t f2key(uint32_t u) {
    return u ^ (uint32_t)(((int32_t)u >> 31) | 0x80000000u);
}
static __device__ __forceinline__ float key2f(uint32_t k) {
    uint32_t m = (uint32_t)((int32_t)k >> 31);
    return __uint_as_float(k ^ (0x80000000u | ~m));
}

// Warp-0 suffix-scan over a 256-bin histogram (descending bins). The lane/slot
// where cumulative count (from the top, plus `base`) crosses kk writes
// {bin, residual-k, bin-count}. Call from warp 0 only; caller syncs around it.
static __device__ __forceinline__ void scan_w0(
    const uint32_t* __restrict__ hist, uint32_t base, uint32_t kk,
    uint32_t* sh_bin, uint32_t* sh_krem, uint32_t* sh_cnt, int lane)
{
    const int b0 = 248 - 8 * lane;                       // lane 0 owns top bins
    uint4 p0 = *reinterpret_cast<const uint4*>(hist + b0);
    uint4 p1 = *reinterpret_cast<const uint4*>(hist + b0 + 4);
    uint32_t h[8] = {p1.w, p1.z, p1.y, p1.x, p0.w, p0.z, p0.y, p0.x}; // descending
    uint32_t sum = 0;
    #pragma unroll
    for (int j = 0; j < 8; j++) sum += h[j];
    uint32_t ex = sum;
    #pragma unroll
    for (int off = 1; off < 32; off <<= 1) {
        uint32_t y = __shfl_up_sync(0xFFFFFFFFu, ex, off);
        if (lane >= off) ex += y;
    }
    uint32_t excl = ex - sum + base;                     // exclusive prefix above my chunk
    #pragma unroll
    for (int j = 0; j < 8; j++) {
        uint32_t c = h[j];
        if (kk > excl && kk <= excl + c) {
            *sh_bin  = (uint32_t)(b0 + 7 - j);
            *sh_krem = kk - excl;
            *sh_cnt  = c;
        }
        excl += c;
    }
}

__global__ void __launch_bounds__(NTHREADS, 6)
kwinners_kernel(const float* __restrict__ s, float* __restrict__ out)
{
    __shared__ uint32_t hist[256];
    __shared__ float    hval[256];          // representative value per bin
    __shared__ uint32_t wabove[NWARPS];
    __shared__ float    fcand[FC_CAP];
    __shared__ uint32_t sh_bin, sh_krem, sh_cnt, sh_fcnt;
    __shared__ float    sh_T;

    const int tid  = threadIdx.x;
    const int lane = tid & 31;
    const int wid  = tid >> 5;
    const unsigned FULL = 0xFFFFFFFFu;

    const size_t row = blockIdx.x;
    const float4* __restrict__ src = reinterpret_cast<const float4*>(s)  + row * (NEURONS / 4);
    float4* __restrict__       dst = reinterpret_cast<float4*>(out)      + row * (NEURONS / 4);

    hist[tid] = 0u;
    if (tid == 0) { sh_bin = SENT; sh_fcnt = 0u; }
    __syncthreads();                                        // sync #1

    // ---- pass 1: integer-bit classify; sparse in-window histogram ----
    unsigned above = 0;
    #pragma unroll
    for (int i = 0; i < VPT; i++) {
        float4 v = src[tid + i * NTHREADS];
        float xs[4] = {v.x, v.y, v.z, v.w};
        #pragma unroll
        for (int j = 0; j < 4; j++) {
            int b = (__float_as_int(xs[j]) >> WIN_SHIFT) - WIN_BASE;  // <0 below, >=256 above
            above += (b >= 256);
            if ((unsigned)b < 256u) { atomicAdd(&hist[b], 1u); hval[b] = xs[j]; }
        }
    }
    above = __reduce_add_sync(FULL, above);
    if (lane == 0) wabove[wid] = above;
    __syncthreads();                                        // sync #2

    if (wid == 0) {
        uint32_t bse = (lane < NWARPS) ? wabove[lane] : 0u;
        bse = __reduce_add_sync(FULL, bse);
        scan_w0(hist, bse, KSEL, &sh_bin, &sh_krem, &sh_cnt, lane);
    }
    __syncthreads();                                        // sync #3

    float T;
    const uint32_t B = sh_bin;
    if (B != SENT && sh_cnt <= FC_CAP) {
        if (sh_cnt == 1u) {
            T = hval[B];                                    // sole element of crossing bin
        } else {
            const uint32_t krem = sh_krem;
            // collect the few bin-B elements (row re-read hits L1), exact rank-select
            #pragma unroll
            for (int i = 0; i < VPT; i++) {
                float4 v = src[tid + i * NTHREADS];
                float xs[4] = {v.x, v.y, v.z, v.w};
                #pragma unroll
                for (int j = 0; j < 4; j++) {
                    int b = (__float_as_int(xs[j]) >> WIN_SHIFT) - WIN_BASE;
                    if (b == (int)B) fcand[atomicAdd(&sh_fcnt, 1u)] = xs[j];
                }
            }
            __syncthreads();
            const int n = (int)sh_fcnt;                     // == sh_cnt <= FC_CAP
            if (tid < n) {
                float mine = fcand[tid];
                int g = 0, eq = 0;
                for (int j = 0; j < n; j++) {
                    float o = fcand[j];
                    g  += (o > mine);
                    eq += (o == mine);
                }
                if ((uint32_t)g < krem && (uint32_t)(g + eq) >= krem) sh_T = mine;
            }
            __syncthreads();
            T = sh_T;
        }
    } else {
        // ---- exact 4-pass radix-select fallback (window miss / huge tie mass) ----
        uint32_t prefix = 0, kk = KSEL;
        for (int shift = 24; shift >= 0; shift -= 8) {
            __syncthreads();
            hist[tid] = 0u;
            if (tid == 0) sh_bin = SENT;
            __syncthreads();
            #pragma unroll
            for (int i = 0; i < VPT; i++) {
                float4 v = src[tid + i * NTHREADS];
                float xs[4] = {v.x, v.y, v.z, v.w};
                #pragma unroll
                for (int j = 0; j < 4; j++) {
                    uint32_t key = f2key(__float_as_uint(xs[j]));
                    bool valid = (shift == 24) || ((key >> (shift + 8)) == prefix);
                    if (valid) atomicAdd(&hist[(key >> shift) & 0xFFu], 1u);
                }
            }
            __syncthreads();
            if (wid == 0) scan_w0(hist, 0u, kk, &sh_bin, &sh_krem, &sh_cnt, lane);
            __syncthreads();
            prefix = (prefix << 8) | sh_bin;
            kk = sh_krem;
        }
        T = key2f(prefix);
    }

    // ---- apply threshold; last-use loads, streaming stores ----
    #pragma unroll
    for (int i = 0; i < VPT; i++) {
        float4 v = __ldcs(&src[tid + i * NTHREADS]);
        float4 o;
        o.x = (v.x >= T) ? v.x : 0.0f;
        o.y = (v.y >= T) ? v.y : 0.0f;
        o.z = (v.z >= T) ? v.z : 0.0f;
        o.w = (v.w >= T) ? v.w : 0.0f;
        __stcs(&dst[tid + i * NTHREADS], o);
    }
}

extern "C" void kernel_launch(void* const* d_in, const int* in_sizes, int n_in,
                              void* d_out, int out_size)
{
    const float* s = (const float*)d_in[0];
    float* out = (float*)d_out;
    const int rows = out_size / NEURONS;   // 16384
    kwinners_kernel<<<rows, NTHREADS>>>(s, out);
}